// round 7
// baseline (speedup 1.0000x reference)
#include <cuda_runtime.h>
#include <cuda_bf16.h>
#include <cstdint>

// ---------------------------------------------------------------------------
// TransformerBlock: B=2, S=2048, D=768, H=12, Hd=64, D_FF=3072, fp32 I/O.
// Round 6: 128x128 GEMM tiles + 3-stage pipelines + single wconv launch.
// ---------------------------------------------------------------------------

#define D_MODEL 768
#define D_FF    3072
#define SEQ     2048
#define BATCH   2
#define NHEAD   12
#define HDIM    64
#define MROWS   (BATCH * SEQ)   // 4096
#define LDQKV   (3 * D_MODEL)   // 2304

// ---------------- scratch (static device globals; no allocation) -----------
__device__ float g_x1  [MROWS * D_MODEL];
__device__ float g_bqkv[LDQKV];

__device__ __nv_bfloat16 g_ln1h[MROWS * D_MODEL], g_ln1l[MROWS * D_MODEL];
__device__ __nv_bfloat16 g_qkvh[MROWS * LDQKV],   g_qkvl[MROWS * LDQKV];
__device__ __nv_bfloat16 g_attnh[MROWS * D_MODEL], g_attnl[MROWS * D_MODEL];
__device__ __nv_bfloat16 g_ln2h[MROWS * D_MODEL], g_ln2l[MROWS * D_MODEL];
__device__ __nv_bfloat16 g_ff1h[MROWS * D_FF],   g_ff1l[MROWS * D_FF];

__device__ __nv_bfloat16 g_wqkvth[LDQKV * D_MODEL], g_wqkvtl[LDQKV * D_MODEL];
__device__ __nv_bfloat16 g_woth[D_MODEL * D_MODEL], g_wotl[D_MODEL * D_MODEL];
__device__ __nv_bfloat16 g_w1th[D_FF * D_MODEL],    g_w1tl[D_FF * D_MODEL];
__device__ __nv_bfloat16 g_w2th[D_MODEL * D_FF],    g_w2tl[D_MODEL * D_FF];

// ---------------------------------------------------------------------------
// PTX helpers
// ---------------------------------------------------------------------------
__device__ __forceinline__ uint32_t smem_u32(const void* p) {
    uint32_t a;
    asm("{ .reg .u64 t; cvta.to.shared.u64 t, %1; cvt.u32.u64 %0, t; }"
        : "=r"(a) : "l"(p));
    return a;
}
__device__ __forceinline__ void ldsm_x4(uint32_t addr, uint32_t* r) {
    asm volatile("ldmatrix.sync.aligned.m8n8.x4.shared.b16 {%0,%1,%2,%3}, [%4];"
        : "=r"(r[0]), "=r"(r[1]), "=r"(r[2]), "=r"(r[3]) : "r"(addr));
}
__device__ __forceinline__ void ldsm_x4_t(uint32_t addr, uint32_t* r) {
    asm volatile("ldmatrix.sync.aligned.m8n8.x4.trans.shared.b16 {%0,%1,%2,%3}, [%4];"
        : "=r"(r[0]), "=r"(r[1]), "=r"(r[2]), "=r"(r[3]) : "r"(addr));
}
__device__ __forceinline__ void mma16816(float* d, const uint32_t* a, const uint32_t* b) {
    asm volatile("mma.sync.aligned.m16n8k16.row.col.f32.bf16.bf16.f32 "
        "{%0,%1,%2,%3}, {%4,%5,%6,%7}, {%8,%9}, {%0,%1,%2,%3};"
        : "+f"(d[0]), "+f"(d[1]), "+f"(d[2]), "+f"(d[3])
        : "r"(a[0]), "r"(a[1]), "r"(a[2]), "r"(a[3]), "r"(b[0]), "r"(b[1]));
}
__device__ __forceinline__ void cpasync16(uint32_t dst, const void* src) {
    asm volatile("cp.async.cg.shared.global [%0], [%1], 16;" :: "r"(dst), "l"(src));
}
#define CP_COMMIT()  asm volatile("cp.async.commit_group;" ::: "memory")
#define CP_WAIT(n)   asm volatile("cp.async.wait_group %0;" :: "n"(n) : "memory")

__device__ __forceinline__ uint32_t packsplit(float x, float y, uint32_t& lo) {
    __nv_bfloat162 h = __floats2bfloat162_rn(x, y);
    float hx = __bfloat162float(h.x), hy = __bfloat162float(h.y);
    __nv_bfloat162 l = __floats2bfloat162_rn(x - hx, y - hy);
    lo = *(uint32_t*)&l;
    return *(uint32_t*)&h;
}

// ---------------------------------------------------------------------------
// LayerNorm -> bf16 hi/lo
// ---------------------------------------------------------------------------
__global__ void __launch_bounds__(256)
ln_kernel(const float* __restrict__ x, const float* __restrict__ g,
          const float* __restrict__ b, __nv_bfloat16* __restrict__ outH,
          __nv_bfloat16* __restrict__ outL)
{
    int row = blockIdx.x;
    const float* xr = x + (size_t)row * D_MODEL;
    int tid = threadIdx.x;
    float v[3];
    float s = 0.f, s2 = 0.f;
#pragma unroll
    for (int i = 0; i < 3; i++) {
        v[i] = xr[tid + i * 256];
        s  += v[i];
        s2 += v[i] * v[i];
    }
    int lane = tid & 31, warp = tid >> 5;
#pragma unroll
    for (int o = 16; o; o >>= 1) {
        s  += __shfl_xor_sync(0xffffffffu, s,  o);
        s2 += __shfl_xor_sync(0xffffffffu, s2, o);
    }
    __shared__ float rs[8], rs2[8], mu_s, rstd_s;
    if (lane == 0) { rs[warp] = s; rs2[warp] = s2; }
    __syncthreads();
    if (tid == 0) {
        float a = 0.f, c = 0.f;
#pragma unroll
        for (int i = 0; i < 8; i++) { a += rs[i]; c += rs2[i]; }
        float mu  = a * (1.f / D_MODEL);
        float var = c * (1.f / D_MODEL) - mu * mu;
        mu_s = mu;
        rstd_s = rsqrtf(var + 1e-5f);
    }
    __syncthreads();
    float mu = mu_s, rstd = rstd_s;
#pragma unroll
    for (int i = 0; i < 3; i++) {
        int d = tid + i * 256;
        float y = (v[i] - mu) * rstd * g[d] + b[d];
        __nv_bfloat16 h = __float2bfloat16(y);
        float lo = y - __bfloat162float(h);
        size_t o = (size_t)row * D_MODEL + d;
        outH[o] = h;
        outL[o] = __float2bfloat16(lo);
    }
}

// ---------------------------------------------------------------------------
// Single-launch weight transpose + hi/lo split for all 6 weights.
// Tile map (32x32 tiles): [0,576)x4 : wq wk wv wo ; then w1 (2304), w2 (2304).
// ---------------------------------------------------------------------------
__global__ void __launch_bounds__(256)
wconv_all(const float* __restrict__ wq, const float* __restrict__ wk,
          const float* __restrict__ wv, const float* __restrict__ wo,
          const float* __restrict__ w1, const float* __restrict__ w2,
          __nv_bfloat16* __restrict__ qkvh, __nv_bfloat16* __restrict__ qkvl,
          __nv_bfloat16* __restrict__ woh,  __nv_bfloat16* __restrict__ wol,
          __nv_bfloat16* __restrict__ w1h,  __nv_bfloat16* __restrict__ w1l,
          __nv_bfloat16* __restrict__ w2h,  __nv_bfloat16* __restrict__ w2l)
{
    int bid = blockIdx.x;
    const float* W;
    __nv_bfloat16 *TH, *TL;
    int K, N, tile;
    if (bid < 2304) {
        int wsel = bid / 576;
        tile = bid - wsel * 576;
        K = 768; N = 768;
        if (wsel == 0)      { W = wq; TH = qkvh;                     TL = qkvl; }
        else if (wsel == 1) { W = wk; TH = qkvh + D_MODEL * D_MODEL; TL = qkvl + D_MODEL * D_MODEL; }
        else if (wsel == 2) { W = wv; TH = qkvh + 2*D_MODEL*D_MODEL; TL = qkvl + 2*D_MODEL*D_MODEL; }
        else                { W = wo; TH = woh;                      TL = wol; }
    } else if (bid < 4608) {
        tile = bid - 2304; K = 768; N = 3072; W = w1; TH = w1h; TL = w1l;
    } else {
        tile = bid - 4608; K = 3072; N = 768; W = w2; TH = w2h; TL = w2l;
    }
    int tilesX = N >> 5;
    int n0 = (tile % tilesX) * 32;
    int k0 = (tile / tilesX) * 32;

    __shared__ float t[32][33];
    int x = threadIdx.x, y = threadIdx.y;
#pragma unroll
    for (int i = y; i < 32; i += 8)
        t[i][x] = W[(size_t)(k0 + i) * N + n0 + x];
    __syncthreads();
#pragma unroll
    for (int i = y; i < 32; i += 8) {
        float v = t[x][i];          // = W[k0+x][n0+i]
        __nv_bfloat16 h = __float2bfloat16(v);
        float lo = v - __bfloat162float(h);
        size_t o = (size_t)(n0 + i) * K + k0 + x;
        TH[o] = h;
        TL[o] = __float2bfloat16(lo);
    }
}

// ---------------------------------------------------------------------------
// HMMA bf16x3 GEMM: C[M,N] = A[M,K] x B[N,K]^T (both K-major, hi/lo bf16)
// CTA tile 128x128, 8 warps x (64m x 32n), KC=32, 3-stage cp.async pipeline.
// ---------------------------------------------------------------------------
#define KC      32
#define A_HI    0
#define A_LO    (128 * 80)                  // 10240 B
#define B_HI    (2 * 128 * 80)              // 20480 B
#define B_LO    (3 * 128 * 80)              // 30720 B
#define STAGE_B (4 * 128 * 80)              // 40960 B per stage
#define GEMM_SMEM (3 * STAGE_B)             // 122880 B

template<bool RELU, bool RES, bool OUTF, bool OUTB>
__global__ void __launch_bounds__(256)
gemm_tc(const __nv_bfloat16* __restrict__ Ah, const __nv_bfloat16* __restrict__ Al,
        const __nv_bfloat16* __restrict__ Bh, const __nv_bfloat16* __restrict__ Bl,
        const float* __restrict__ bias, const float* __restrict__ res,
        float* __restrict__ C, __nv_bfloat16* __restrict__ Ch, __nv_bfloat16* __restrict__ Cl,
        int M, int N, int K)
{
    extern __shared__ char sm[];
    uint32_t smBase = smem_u32(sm);

    int tid = threadIdx.x;
    int wid = tid >> 5, lane = tid & 31;
    int mBase = blockIdx.y * 128;
    int nBase = blockIdx.x * 128;

    const char* gAh = (const char*)(Ah + (size_t)mBase * K);
    const char* gAl = (const char*)(Al + (size_t)mBase * K);
    const char* gBh = (const char*)(Bh + (size_t)nBase * K);
    const char* gBl = (const char*)(Bl + (size_t)nBase * K);

    int nch = K / KC;

    auto issue = [&](int c) {
        uint32_t st = smBase + (c % 3) * STAGE_B;
        size_t kOff = (size_t)c * KC * 2;
#pragma unroll
        for (int i = 0; i < 2; i++) {
            int chunk = tid + i * 256;          // 0..511
            int r = chunk >> 2, seg = chunk & 3;
            size_t go = (size_t)r * (size_t)(K * 2) + kOff + seg * 16;
            uint32_t so = r * 80 + seg * 16;
            cpasync16(st + A_HI + so, gAh + go);
            cpasync16(st + A_LO + so, gAl + go);
            cpasync16(st + B_HI + so, gBh + go);
            cpasync16(st + B_LO + so, gBl + go);
        }
    };

    float acc[4][4][4];
#pragma unroll
    for (int i = 0; i < 4; i++)
#pragma unroll
        for (int j = 0; j < 4; j++)
#pragma unroll
            for (int q = 0; q < 4; q++) acc[i][j][q] = 0.f;

    int wm = wid & 1;        // m offset 64*wm
    int wn = wid >> 1;       // n offset 32*wn

    int laneM  = (lane & 7) + ((lane >> 3) & 1) * 8;
    int laneKA = (lane >> 4) * 8;
    int laneNB = (lane >> 4) * 8 + (lane & 7);
    int laneKB = ((lane >> 3) & 1) * 8;

    issue(0); CP_COMMIT();
    issue(1); CP_COMMIT();

    for (int c = 0; c < nch; c++) {
        CP_WAIT(1);
        __syncthreads();
        if (c + 2 < nch) { issue(c + 2); CP_COMMIT(); }

        uint32_t st = smBase + (c % 3) * STAGE_B;
#pragma unroll
        for (int ks = 0; ks < KC; ks += 16) {
            uint32_t ahi[4][4], alo[4][4], bhi[2][4], blo[2][4];
#pragma unroll
            for (int mt = 0; mt < 4; mt++) {
                int row = wm * 64 + mt * 16 + laneM;
                uint32_t col = (uint32_t)(ks + laneKA) * 2;
                ldsm_x4(st + A_HI + row * 80 + col, ahi[mt]);
                ldsm_x4(st + A_LO + row * 80 + col, alo[mt]);
            }
#pragma unroll
            for (int ntp = 0; ntp < 2; ntp++) {
                int n = wn * 32 + ntp * 16 + laneNB;
                uint32_t col = (uint32_t)(ks + laneKB) * 2;
                ldsm_x4(st + B_HI + n * 80 + col, bhi[ntp]);
                ldsm_x4(st + B_LO + n * 80 + col, blo[ntp]);
            }
#pragma unroll
            for (int mt = 0; mt < 4; mt++)
#pragma unroll
                for (int ntp = 0; ntp < 2; ntp++)
#pragma unroll
                    for (int h = 0; h < 2; h++) {
                        float* d = acc[mt][ntp * 2 + h];
                        mma16816(d, ahi[mt], &bhi[ntp][h * 2]);
                        mma16816(d, ahi[mt], &blo[ntp][h * 2]);
                        mma16816(d, alo[mt], &bhi[ntp][h * 2]);
                    }
        }
        __syncthreads();
    }

#pragma unroll
    for (int mt = 0; mt < 4; mt++) {
        int r0 = mBase + wm * 64 + mt * 16 + (lane >> 2);
#pragma unroll
        for (int nt = 0; nt < 4; nt++) {
            int col = nBase + wn * 32 + nt * 8 + (lane & 3) * 2;
            float bx = bias[col], by = bias[col + 1];
            float* d = acc[mt][nt];
#pragma unroll
            for (int hrow = 0; hrow < 2; hrow++) {
                int r = r0 + hrow * 8;
                size_t off = (size_t)r * N + col;
                float vx = d[hrow * 2 + 0] + bx;
                float vy = d[hrow * 2 + 1] + by;
                if (RES) {
                    float2 rv = *(const float2*)(res + off);
                    vx += rv.x; vy += rv.y;
                }
                if (RELU) { vx = fmaxf(vx, 0.f); vy = fmaxf(vy, 0.f); }
                if (OUTF) {
                    float2 o; o.x = vx; o.y = vy;
                    *(float2*)(C + off) = o;
                }
                if (OUTB) {
                    uint32_t lo;
                    uint32_t hi = packsplit(vx, vy, lo);
                    *(uint32_t*)(Ch + off) = hi;
                    *(uint32_t*)(Cl + off) = lo;
                }
            }
        }
    }
}

// ---------------------------------------------------------------------------
// HMMA causal flash attention. CTA: 64 q-rows x one (b,h); 4 warps.
// 64-kpos tiles, 3-stage cp.async pipeline with early issue.
// ---------------------------------------------------------------------------
#define ATT_PITCH 144
#define ATT_TILE  (64 * ATT_PITCH)         // 9216 B
#define ATT_STAGE (4 * ATT_TILE)           // 36864 B
#define ATT_SMEM  (3 * ATT_STAGE)          // 110592 B

__global__ void __launch_bounds__(128)
attn_tc(const __nv_bfloat16* __restrict__ QKVh, const __nv_bfloat16* __restrict__ QKVl,
        __nv_bfloat16* __restrict__ OH, __nv_bfloat16* __restrict__ OL)
{
    extern __shared__ char sm[];
    uint32_t smBase = smem_u32(sm);

    int b = blockIdx.z, h = blockIdx.y;
    int qb = gridDim.x - 1 - blockIdx.x;     // heavy blocks first
    int tid = threadIdx.x, w = tid >> 5, lane = tid & 31;

    size_t rowBase = (size_t)b * SEQ * LDQKV;
    const __nv_bfloat16* Qh = QKVh + rowBase + h * HDIM;
    const __nv_bfloat16* Ql = QKVl + rowBase + h * HDIM;
    const __nv_bfloat16* Kh = QKVh + rowBase + D_MODEL + h * HDIM;
    const __nv_bfloat16* Kl = QKVl + rowBase + D_MODEL + h * HDIM;
    const __nv_bfloat16* Vh = QKVh + rowBase + 2 * D_MODEL + h * HDIM;
    const __nv_bfloat16* Vl = QKVl + rowBase + 2 * D_MODEL + h * HDIM;

    uint32_t qhi[4][4], qlo[4][4];
    {
        __nv_bfloat162 sc = __floats2bfloat162_rn(0.125f, 0.125f);
        int rA = qb * 64 + w * 16 + (lane >> 2);
        int cA = (lane & 3) * 2;
#pragma unroll
        for (int kt = 0; kt < 4; kt++) {
            int c0 = kt * 16 + cA;
            const __nv_bfloat16* p00 = Qh + (size_t)rA * LDQKV + c0;
            const __nv_bfloat16* p10 = Qh + (size_t)(rA + 8) * LDQKV + c0;
            const __nv_bfloat16* l00 = Ql + (size_t)rA * LDQKV + c0;
            const __nv_bfloat16* l10 = Ql + (size_t)(rA + 8) * LDQKV + c0;
            __nv_bfloat162 v;
            v = __hmul2(*(const __nv_bfloat162*)(p00),     sc); qhi[kt][0] = *(uint32_t*)&v;
            v = __hmul2(*(const __nv_bfloat162*)(p10),     sc); qhi[kt][1] = *(uint32_t*)&v;
            v = __hmul2(*(const __nv_bfloat162*)(p00 + 8), sc); qhi[kt][2] = *(uint32_t*)&v;
            v = __hmul2(*(const __nv_bfloat162*)(p10 + 8), sc); qhi[kt][3] = *(uint32_t*)&v;
            v = __hmul2(*(const __nv_bfloat162*)(l00),     sc); qlo[kt][0] = *(uint32_t*)&v;
            v = __hmul2(*(const __nv_bfloat162*)(l10),     sc); qlo[kt][1] = *(uint32_t*)&v;
            v = __hmul2(*(const __nv_bfloat162*)(l00 + 8), sc); qlo[kt][2] = *(uint32_t*)&v;
            v = __hmul2(*(const __nv_bfloat162*)(l10 + 8), sc); qlo[kt][3] = *(uint32_t*)&v;
        }
    }

    auto issueTile = [&](int t) {
        uint32_t st = smBase + (t % 3) * ATT_STAGE;
        int k0 = t * 64;
#pragma unroll
        for (int i = 0; i < 4; i++) {
            int chunk = tid + i * 128;        // 0..511
            int r = chunk >> 3, seg = chunk & 7;
            size_t go = (size_t)(k0 + r) * LDQKV;
            uint32_t so = r * ATT_PITCH + seg * 16;
            cpasync16(st + 0 * ATT_TILE + so, (const char*)(Kh + go) + seg * 16);
            cpasync16(st + 1 * ATT_TILE + so, (const char*)(Kl + go) + seg * 16);
            cpasync16(st + 2 * ATT_TILE + so, (const char*)(Vh + go) + seg * 16);
            cpasync16(st + 3 * ATT_TILE + so, (const char*)(Vl + go) + seg * 16);
        }
    };

    float o[8][4];
#pragma unroll
    for (int i = 0; i < 8; i++)
#pragma unroll
        for (int j = 0; j < 4; j++) o[i][j] = 0.f;
    float m0 = -1e30f, m1 = -1e30f, l0 = 0.f, l1 = 0.f;

    int ntb = qb + 1;
    int laneNB = (lane >> 4) * 8 + (lane & 7);
    int laneKB = ((lane >> 3) & 1) * 8;
    int vr = ((lane >> 3) & 1) * 8 + (lane & 7);
    int vc = ((lane >> 4) & 1) * 8;

    issueTile(0); CP_COMMIT();
    if (ntb > 1) { issueTile(1); CP_COMMIT(); }

    for (int t = 0; t < ntb; t++) {
        if (t + 1 < ntb) { CP_WAIT(1); } else { CP_WAIT(0); }
        __syncthreads();
        if (t + 2 < ntb) { issueTile(t + 2); CP_COMMIT(); }

        uint32_t st = smBase + (t % 3) * ATT_STAGE;

        // ---- S = Q K^T (pre-scaled) ----------------------------------------
        float s[8][4];
#pragma unroll
        for (int i = 0; i < 8; i++)
#pragma unroll
            for (int j = 0; j < 4; j++) s[i][j] = 0.f;

#pragma unroll
        for (int kt = 0; kt < 4; kt++) {
#pragma unroll
            for (int ng = 0; ng < 4; ng++) {
                uint32_t kh[4], kl[4];
                uint32_t ka = st + (ng * 16 + laneNB) * ATT_PITCH + (kt * 16 + laneKB) * 2;
                ldsm_x4(ka, kh);
                ldsm_x4(ka + ATT_TILE, kl);
#pragma unroll
                for (int hf = 0; hf < 2; hf++) {
                    float* d = s[ng * 2 + hf];
                    mma16816(d, qhi[kt], &kh[hf * 2]);
                    mma16816(d, qhi[kt], &kl[hf * 2]);
                    mma16816(d, qlo[kt], &kh[hf * 2]);
                }
            }
        }

        // ---- causal mask (diagonal tile only) ------------------------------
        if (t == qb) {
            int rg0 = qb * 64 + w * 16 + (lane >> 2);
            int rg1 = rg0 + 8;
#pragma unroll
            for (int nt = 0; nt < 8; nt++) {
                int c0 = t * 64 + nt * 8 + (lane & 3) * 2;
                if (c0     > rg0) s[nt][0] = -1e30f;
                if (c0 + 1 > rg0) s[nt][1] = -1e30f;
                if (c0     > rg1) s[nt][2] = -1e30f;
                if (c0 + 1 > rg1) s[nt][3] = -1e30f;
            }
        }

        // ---- online softmax -------------------------------------------------
        float mx0 = m0, mx1 = m1;
#pragma unroll
        for (int nt = 0; nt < 8; nt++) {
            mx0 = fmaxf(mx0, fmaxf(s[nt][0], s[nt][1]));
            mx1 = fmaxf(mx1, fmaxf(s[nt][2], s[nt][3]));
        }
        mx0 = fmaxf(mx0, __shfl_xor_sync(0xffffffffu, mx0, 1));
        mx0 = fmaxf(mx0, __shfl_xor_sync(0xffffffffu, mx0, 2));
        mx1 = fmaxf(mx1, __shfl_xor_sync(0xffffffffu, mx1, 1));
        mx1 = fmaxf(mx1, __shfl_xor_sync(0xffffffffu, mx1, 2));
        float f0 = __expf(m0 - mx0), f1 = __expf(m1 - mx1);
        m0 = mx0; m1 = mx1;

        float rs0 = 0.f, rs1 = 0.f;
#pragma unroll
        for (int nt = 0; nt < 8; nt++) {
            s[nt][0] = __expf(s[nt][0] - mx0);
            s[nt][1] = __expf(s[nt][1] - mx0);
            s[nt][2] = __expf(s[nt][2] - mx1);
            s[nt][3] = __expf(s[nt][3] - mx1);
            rs0 += s[nt][0] + s[nt][1];
            rs1 += s[nt][2] + s[nt][3];
        }
        rs0 += __shfl_xor_sync(0xffffffffu, rs0, 1);
        rs0 += __shfl_xor_sync(0xffffffffu, rs0, 2);
        rs1 += __shfl_xor_sync(0xffffffffu, rs1, 1);
        rs1 += __shfl_xor_sync(0xffffffffu, rs1, 2);
        l0 = l0 * f0 + rs0;
        l1 = l1 * f1 + rs1;

#pragma unroll
        for (int nt = 0; nt < 8; nt++) {
            o[nt][0] *= f0; o[nt][1] *= f0;
            o[nt][2] *= f1; o[nt][3] *= f1;
        }

        // ---- P fragments (hi/lo) -------------------------------------------
        uint32_t phi[4][4], plo[4][4];
#pragma unroll
        for (int kt = 0; kt < 4; kt++) {
            phi[kt][0] = packsplit(s[2*kt][0],   s[2*kt][1],   plo[kt][0]);
            phi[kt][1] = packsplit(s[2*kt][2],   s[2*kt][3],   plo[kt][1]);
            phi[kt][2] = packsplit(s[2*kt+1][0], s[2*kt+1][1], plo[kt][2]);
            phi[kt][3] = packsplit(s[2*kt+1][2], s[2*kt+1][3], plo[kt][3]);
        }

        // ---- O += P V -------------------------------------------------------
#pragma unroll
        for (int kt = 0; kt < 4; kt++) {
#pragma unroll
            for (int dg = 0; dg < 4; dg++) {
                uint32_t vh[4], vl[4];
                uint32_t va = st + 2 * ATT_TILE + (kt * 16 + vr) * ATT_PITCH + (dg * 16 + vc) * 2;
                ldsm_x4_t(va, vh);
                ldsm_x4_t(va + ATT_TILE, vl);
#pragma unroll
                for (int hf = 0; hf < 2; hf++) {
                    float* d = o[dg * 2 + hf];
                    mma16816(d, phi[kt], &vh[hf * 2]);
                    mma16816(d, phi[kt], &vl[hf * 2]);
                    mma16816(d, plo[kt], &vh[hf * 2]);
                }
            }
        }
        __syncthreads();
    }

    // ---- normalize + store bf16 hi/lo --------------------------------------
    float inv0 = 1.f / l0, inv1 = 1.f / l1;
    int ro0 = qb * 64 + w * 16 + (lane >> 2);
    size_t ob0 = ((size_t)(b * SEQ) + ro0) * D_MODEL + h * HDIM;
    size_t ob1 = ob0 + 8 * (size_t)D_MODEL;
#pragma unroll
    for (int nt = 0; nt < 8; nt++) {
        int c = nt * 8 + (lane & 3) * 2;
        uint32_t lo;
        uint32_t hi = packsplit(o[nt][0] * inv0, o[nt][1] * inv0, lo);
        *(uint32_t*)(OH + ob0 + c) = hi;
        *(uint32_t*)(OL + ob0 + c) = lo;
        hi = packsplit(o[nt][2] * inv1, o[nt][3] * inv1, lo);
        *(uint32_t*)(OH + ob1 + c) = hi;
        *(uint32_t*)(OL + ob1 + c) = lo;
    }
}

// ---------------------------------------------------------------------------
// Launch
// ---------------------------------------------------------------------------
extern "C" void kernel_launch(void* const* d_in, const int* in_sizes, int n_in,
                              void* d_out, int out_size)
{
    (void)in_sizes; (void)n_in; (void)out_size;
    const float* x     = (const float*)d_in[0];
    const float* wq    = (const float*)d_in[1];
    const float* bq    = (const float*)d_in[2];
    const float* wk    = (const float*)d_in[3];
    const float* bk    = (const float*)d_in[4];
    const float* wv    = (const float*)d_in[5];
    const float* bv    = (const float*)d_in[6];
    const float* wo    = (const float*)d_in[7];
    const float* bo    = (const float*)d_in[8];
    const float* w1    = (const float*)d_in[9];
    const float* b1    = (const float*)d_in[10];
    const float* w2    = (const float*)d_in[11];
    const float* b2    = (const float*)d_in[12];
    const float* ln1_g = (const float*)d_in[13];
    const float* ln1_b = (const float*)d_in[14];
    const float* ln2_g = (const float*)d_in[15];
    const float* ln2_b = (const float*)d_in[16];
    float* out = (float*)d_out;

    float *x1, *bqkv;
    __nv_bfloat16 *ln1h, *ln1l, *qkvh, *qkvl, *attnh, *attnl, *ln2h, *ln2l, *ff1h, *ff1l;
    __nv_bfloat16 *wqkvth, *wqkvtl, *woth, *wotl, *w1th, *w1tl, *w2th, *w2tl;
    cudaGetSymbolAddress((void**)&x1,   g_x1);
    cudaGetSymbolAddress((void**)&bqkv, g_bqkv);
    cudaGetSymbolAddress((void**)&ln1h, g_ln1h);  cudaGetSymbolAddress((void**)&ln1l, g_ln1l);
    cudaGetSymbolAddress((void**)&qkvh, g_qkvh);  cudaGetSymbolAddress((void**)&qkvl, g_qkvl);
    cudaGetSymbolAddress((void**)&attnh,g_attnh); cudaGetSymbolAddress((void**)&attnl,g_attnl);
    cudaGetSymbolAddress((void**)&ln2h, g_ln2h);  cudaGetSymbolAddress((void**)&ln2l, g_ln2l);
    cudaGetSymbolAddress((void**)&ff1h, g_ff1h);  cudaGetSymbolAddress((void**)&ff1l, g_ff1l);
    cudaGetSymbolAddress((void**)&wqkvth, g_wqkvth); cudaGetSymbolAddress((void**)&wqkvtl, g_wqkvtl);
    cudaGetSymbolAddress((void**)&woth, g_woth);  cudaGetSymbolAddress((void**)&wotl, g_wotl);
    cudaGetSymbolAddress((void**)&w1th, g_w1th);  cudaGetSymbolAddress((void**)&w1tl, g_w1tl);
    cudaGetSymbolAddress((void**)&w2th, g_w2th);  cudaGetSymbolAddress((void**)&w2tl, g_w2tl);

    cudaFuncSetAttribute(gemm_tc<false,false,false,true>,
                         cudaFuncAttributeMaxDynamicSharedMemorySize, GEMM_SMEM);
    cudaFuncSetAttribute(gemm_tc<false,true,true,false>,
                         cudaFuncAttributeMaxDynamicSharedMemorySize, GEMM_SMEM);
    cudaFuncSetAttribute(gemm_tc<true,false,false,true>,
                         cudaFuncAttributeMaxDynamicSharedMemorySize, GEMM_SMEM);
    cudaFuncSetAttribute(attn_tc,
                         cudaFuncAttributeMaxDynamicSharedMemorySize, ATT_SMEM);

    // fused QKV bias
    cudaMemcpyAsync(bqkv,             bq, D_MODEL * sizeof(float), cudaMemcpyDeviceToDevice);
    cudaMemcpyAsync(bqkv + D_MODEL,   bk, D_MODEL * sizeof(float), cudaMemcpyDeviceToDevice);
    cudaMemcpyAsync(bqkv + 2*D_MODEL, bv, D_MODEL * sizeof(float), cudaMemcpyDeviceToDevice);

    // all weight transposes + hi/lo splits in one launch (6912 tiles)
    wconv_all<<<6912, dim3(32, 8)>>>(wq, wk, wv, wo, w1, w2,
                                     wqkvth, wqkvtl, woth, wotl,
                                     w1th, w1tl, w2th, w2tl);

    // 1) LN1 -> bf16 hi/lo
    ln_kernel<<<MROWS, 256>>>(x, ln1_g, ln1_b, ln1h, ln1l);
    // 2) fused QKV projection -> bf16 hi/lo [4096, 2304]
    gemm_tc<false,false,false,true><<<dim3(LDQKV/128, MROWS/128), 256, GEMM_SMEM>>>(
        ln1h, ln1l, wqkvth, wqkvtl, bqkv, nullptr, nullptr, qkvh, qkvl, MROWS, LDQKV, D_MODEL);
    // 3) HMMA causal flash attention -> bf16 hi/lo
    attn_tc<<<dim3(SEQ/64, NHEAD, BATCH), 128, ATT_SMEM>>>(qkvh, qkvl, attnh, attnl);
    // 4) O projection + residual (fp32 x1)
    gemm_tc<false,true,true,false><<<dim3(D_MODEL/128, MROWS/128), 256, GEMM_SMEM>>>(
        attnh, attnl, woth, wotl, bo, x, x1, nullptr, nullptr, MROWS, D_MODEL, D_MODEL);
    // 5) LN2 -> bf16 hi/lo
    ln_kernel<<<MROWS, 256>>>(x1, ln2_g, ln2_b, ln2h, ln2l);
    // 6) FFN up + ReLU -> bf16 hi/lo
    gemm_tc<true,false,false,true><<<dim3(D_FF/128, MROWS/128), 256, GEMM_SMEM>>>(
        ln2h, ln2l, w1th, w1tl, b1, nullptr, nullptr, ff1h, ff1l, MROWS, D_FF, D_MODEL);
    // 7) FFN down + residual -> output (fp32)
    gemm_tc<false,true,true,false><<<dim3(D_MODEL/128, MROWS/128), 256, GEMM_SMEM>>>(
        ff1h, ff1l, w2th, w2tl, b2, x1, out, nullptr, nullptr, MROWS, D_MODEL, D_FF);
}

// round 12
// speedup vs baseline: 1.0941x; 1.0941x over previous
#include <cuda_runtime.h>
#include <cuda_bf16.h>
#include <cstdint>

// ---------------------------------------------------------------------------
// TransformerBlock: B=2, S=2048, D=768, H=12, Hd=64, D_FF=3072, fp32 I/O.
// Round 8: 128x128 GEMM tiles with 2-stage pipeline (2 CTAs/SM),
//          attention 2-stage (3 CTAs/SM), single wconv launch.
// ---------------------------------------------------------------------------

#define D_MODEL 768
#define D_FF    3072
#define SEQ     2048
#define BATCH   2
#define NHEAD   12
#define HDIM    64
#define MROWS   (BATCH * SEQ)   // 4096
#define LDQKV   (3 * D_MODEL)   // 2304

// ---------------- scratch (static device globals; no allocation) -----------
__device__ float g_x1  [MROWS * D_MODEL];
__device__ float g_bqkv[LDQKV];

__device__ __nv_bfloat16 g_ln1h[MROWS * D_MODEL], g_ln1l[MROWS * D_MODEL];
__device__ __nv_bfloat16 g_qkvh[MROWS * LDQKV],   g_qkvl[MROWS * LDQKV];
__device__ __nv_bfloat16 g_attnh[MROWS * D_MODEL], g_attnl[MROWS * D_MODEL];
__device__ __nv_bfloat16 g_ln2h[MROWS * D_MODEL], g_ln2l[MROWS * D_MODEL];
__device__ __nv_bfloat16 g_ff1h[MROWS * D_FF],   g_ff1l[MROWS * D_FF];

__device__ __nv_bfloat16 g_wqkvth[LDQKV * D_MODEL], g_wqkvtl[LDQKV * D_MODEL];
__device__ __nv_bfloat16 g_woth[D_MODEL * D_MODEL], g_wotl[D_MODEL * D_MODEL];
__device__ __nv_bfloat16 g_w1th[D_FF * D_MODEL],    g_w1tl[D_FF * D_MODEL];
__device__ __nv_bfloat16 g_w2th[D_MODEL * D_FF],    g_w2tl[D_MODEL * D_FF];

// ---------------------------------------------------------------------------
// PTX helpers
// ---------------------------------------------------------------------------
__device__ __forceinline__ uint32_t smem_u32(const void* p) {
    uint32_t a;
    asm("{ .reg .u64 t; cvta.to.shared.u64 t, %1; cvt.u32.u64 %0, t; }"
        : "=r"(a) : "l"(p));
    return a;
}
__device__ __forceinline__ void ldsm_x4(uint32_t addr, uint32_t* r) {
    asm volatile("ldmatrix.sync.aligned.m8n8.x4.shared.b16 {%0,%1,%2,%3}, [%4];"
        : "=r"(r[0]), "=r"(r[1]), "=r"(r[2]), "=r"(r[3]) : "r"(addr));
}
__device__ __forceinline__ void ldsm_x4_t(uint32_t addr, uint32_t* r) {
    asm volatile("ldmatrix.sync.aligned.m8n8.x4.trans.shared.b16 {%0,%1,%2,%3}, [%4];"
        : "=r"(r[0]), "=r"(r[1]), "=r"(r[2]), "=r"(r[3]) : "r"(addr));
}
__device__ __forceinline__ void mma16816(float* d, const uint32_t* a, const uint32_t* b) {
    asm volatile("mma.sync.aligned.m16n8k16.row.col.f32.bf16.bf16.f32 "
        "{%0,%1,%2,%3}, {%4,%5,%6,%7}, {%8,%9}, {%0,%1,%2,%3};"
        : "+f"(d[0]), "+f"(d[1]), "+f"(d[2]), "+f"(d[3])
        : "r"(a[0]), "r"(a[1]), "r"(a[2]), "r"(a[3]), "r"(b[0]), "r"(b[1]));
}
__device__ __forceinline__ void cpasync16(uint32_t dst, const void* src) {
    asm volatile("cp.async.cg.shared.global [%0], [%1], 16;" :: "r"(dst), "l"(src));
}
#define CP_COMMIT()  asm volatile("cp.async.commit_group;" ::: "memory")
#define CP_WAIT(n)   asm volatile("cp.async.wait_group %0;" :: "n"(n) : "memory")

__device__ __forceinline__ uint32_t packsplit(float x, float y, uint32_t& lo) {
    __nv_bfloat162 h = __floats2bfloat162_rn(x, y);
    float hx = __bfloat162float(h.x), hy = __bfloat162float(h.y);
    __nv_bfloat162 l = __floats2bfloat162_rn(x - hx, y - hy);
    lo = *(uint32_t*)&l;
    return *(uint32_t*)&h;
}

// ---------------------------------------------------------------------------
// LayerNorm -> bf16 hi/lo
// ---------------------------------------------------------------------------
__global__ void __launch_bounds__(256)
ln_kernel(const float* __restrict__ x, const float* __restrict__ g,
          const float* __restrict__ b, __nv_bfloat16* __restrict__ outH,
          __nv_bfloat16* __restrict__ outL)
{
    int row = blockIdx.x;
    const float* xr = x + (size_t)row * D_MODEL;
    int tid = threadIdx.x;
    float v[3];
    float s = 0.f, s2 = 0.f;
#pragma unroll
    for (int i = 0; i < 3; i++) {
        v[i] = xr[tid + i * 256];
        s  += v[i];
        s2 += v[i] * v[i];
    }
    int lane = tid & 31, warp = tid >> 5;
#pragma unroll
    for (int o = 16; o; o >>= 1) {
        s  += __shfl_xor_sync(0xffffffffu, s,  o);
        s2 += __shfl_xor_sync(0xffffffffu, s2, o);
    }
    __shared__ float rs[8], rs2[8], mu_s, rstd_s;
    if (lane == 0) { rs[warp] = s; rs2[warp] = s2; }
    __syncthreads();
    if (tid == 0) {
        float a = 0.f, c = 0.f;
#pragma unroll
        for (int i = 0; i < 8; i++) { a += rs[i]; c += rs2[i]; }
        float mu  = a * (1.f / D_MODEL);
        float var = c * (1.f / D_MODEL) - mu * mu;
        mu_s = mu;
        rstd_s = rsqrtf(var + 1e-5f);
    }
    __syncthreads();
    float mu = mu_s, rstd = rstd_s;
#pragma unroll
    for (int i = 0; i < 3; i++) {
        int d = tid + i * 256;
        float y = (v[i] - mu) * rstd * g[d] + b[d];
        __nv_bfloat16 h = __float2bfloat16(y);
        float lo = y - __bfloat162float(h);
        size_t o = (size_t)row * D_MODEL + d;
        outH[o] = h;
        outL[o] = __float2bfloat16(lo);
    }
}

// ---------------------------------------------------------------------------
// Single-launch weight transpose + hi/lo split for all 6 weights.
// ---------------------------------------------------------------------------
__global__ void __launch_bounds__(256)
wconv_all(const float* __restrict__ wq, const float* __restrict__ wk,
          const float* __restrict__ wv, const float* __restrict__ wo,
          const float* __restrict__ w1, const float* __restrict__ w2,
          __nv_bfloat16* __restrict__ qkvh, __nv_bfloat16* __restrict__ qkvl,
          __nv_bfloat16* __restrict__ woh,  __nv_bfloat16* __restrict__ wol,
          __nv_bfloat16* __restrict__ w1h,  __nv_bfloat16* __restrict__ w1l,
          __nv_bfloat16* __restrict__ w2h,  __nv_bfloat16* __restrict__ w2l)
{
    int bid = blockIdx.x;
    const float* W;
    __nv_bfloat16 *TH, *TL;
    int K, N, tile;
    if (bid < 2304) {
        int wsel = bid / 576;
        tile = bid - wsel * 576;
        K = 768; N = 768;
        if (wsel == 0)      { W = wq; TH = qkvh;                     TL = qkvl; }
        else if (wsel == 1) { W = wk; TH = qkvh + D_MODEL * D_MODEL; TL = qkvl + D_MODEL * D_MODEL; }
        else if (wsel == 2) { W = wv; TH = qkvh + 2*D_MODEL*D_MODEL; TL = qkvl + 2*D_MODEL*D_MODEL; }
        else                { W = wo; TH = woh;                      TL = wol; }
    } else if (bid < 4608) {
        tile = bid - 2304; K = 768; N = 3072; W = w1; TH = w1h; TL = w1l;
    } else {
        tile = bid - 4608; K = 3072; N = 768; W = w2; TH = w2h; TL = w2l;
    }
    int tilesX = N >> 5;
    int n0 = (tile % tilesX) * 32;
    int k0 = (tile / tilesX) * 32;

    __shared__ float t[32][33];
    int x = threadIdx.x, y = threadIdx.y;
#pragma unroll
    for (int i = y; i < 32; i += 8)
        t[i][x] = W[(size_t)(k0 + i) * N + n0 + x];
    __syncthreads();
#pragma unroll
    for (int i = y; i < 32; i += 8) {
        float v = t[x][i];          // = W[k0+x][n0+i]
        __nv_bfloat16 h = __float2bfloat16(v);
        float lo = v - __bfloat162float(h);
        size_t o = (size_t)(n0 + i) * K + k0 + x;
        TH[o] = h;
        TL[o] = __float2bfloat16(lo);
    }
}

// ---------------------------------------------------------------------------
// HMMA bf16x3 GEMM: C[M,N] = A[M,K] x B[N,K]^T (both K-major, hi/lo bf16)
// CTA tile 128x128, 8 warps x (64m x 32n), KC=32, 2-stage cp.async pipeline.
// SMEM 81920 B -> 2 CTAs/SM.
// ---------------------------------------------------------------------------
#define KC      32
#define A_HI    0
#define A_LO    (128 * 80)                  // 10240 B
#define B_HI    (2 * 128 * 80)              // 20480 B
#define B_LO    (3 * 128 * 80)              // 30720 B
#define STAGE_B (4 * 128 * 80)              // 40960 B per stage
#define GEMM_SMEM (2 * STAGE_B)             // 81920 B

template<bool RELU, bool RES, bool OUTF, bool OUTB>
__global__ void __launch_bounds__(256)
gemm_tc(const __nv_bfloat16* __restrict__ Ah, const __nv_bfloat16* __restrict__ Al,
        const __nv_bfloat16* __restrict__ Bh, const __nv_bfloat16* __restrict__ Bl,
        const float* __restrict__ bias, const float* __restrict__ res,
        float* __restrict__ C, __nv_bfloat16* __restrict__ Ch, __nv_bfloat16* __restrict__ Cl,
        int M, int N, int K)
{
    extern __shared__ char sm[];
    uint32_t smBase = smem_u32(sm);

    int tid = threadIdx.x;
    int wid = tid >> 5, lane = tid & 31;
    int mBase = blockIdx.y * 128;
    int nBase = blockIdx.x * 128;

    const char* gAh = (const char*)(Ah + (size_t)mBase * K);
    const char* gAl = (const char*)(Al + (size_t)mBase * K);
    const char* gBh = (const char*)(Bh + (size_t)nBase * K);
    const char* gBl = (const char*)(Bl + (size_t)nBase * K);

    int nch = K / KC;

    auto issue = [&](int c) {
        uint32_t st = smBase + (c & 1) * STAGE_B;
        size_t kOff = (size_t)c * KC * 2;
#pragma unroll
        for (int i = 0; i < 2; i++) {
            int chunk = tid + i * 256;          // 0..511
            int r = chunk >> 2, seg = chunk & 3;
            size_t go = (size_t)r * (size_t)(K * 2) + kOff + seg * 16;
            uint32_t so = r * 80 + seg * 16;
            cpasync16(st + A_HI + so, gAh + go);
            cpasync16(st + A_LO + so, gAl + go);
            cpasync16(st + B_HI + so, gBh + go);
            cpasync16(st + B_LO + so, gBl + go);
        }
    };

    float acc[4][4][4];
#pragma unroll
    for (int i = 0; i < 4; i++)
#pragma unroll
        for (int j = 0; j < 4; j++)
#pragma unroll
            for (int q = 0; q < 4; q++) acc[i][j][q] = 0.f;

    int wm = wid & 1;        // m offset 64*wm
    int wn = wid >> 1;       // n offset 32*wn

    int laneM  = (lane & 7) + ((lane >> 3) & 1) * 8;
    int laneKA = (lane >> 4) * 8;
    int laneNB = (lane >> 4) * 8 + (lane & 7);
    int laneKB = ((lane >> 3) & 1) * 8;

    issue(0); CP_COMMIT();

    for (int c = 0; c < nch; c++) {
        if (c + 1 < nch) { issue(c + 1); CP_COMMIT(); CP_WAIT(1); }
        else             { CP_WAIT(0); }
        __syncthreads();

        uint32_t st = smBase + (c & 1) * STAGE_B;
#pragma unroll
        for (int ks = 0; ks < KC; ks += 16) {
            uint32_t ahi[4][4], alo[4][4], bhi[2][4], blo[2][4];
#pragma unroll
            for (int mt = 0; mt < 4; mt++) {
                int row = wm * 64 + mt * 16 + laneM;
                uint32_t col = (uint32_t)(ks + laneKA) * 2;
                ldsm_x4(st + A_HI + row * 80 + col, ahi[mt]);
                ldsm_x4(st + A_LO + row * 80 + col, alo[mt]);
            }
#pragma unroll
            for (int ntp = 0; ntp < 2; ntp++) {
                int n = wn * 32 + ntp * 16 + laneNB;
                uint32_t col = (uint32_t)(ks + laneKB) * 2;
                ldsm_x4(st + B_HI + n * 80 + col, bhi[ntp]);
                ldsm_x4(st + B_LO + n * 80 + col, blo[ntp]);
            }
#pragma unroll
            for (int mt = 0; mt < 4; mt++)
#pragma unroll
                for (int ntp = 0; ntp < 2; ntp++)
#pragma unroll
                    for (int h = 0; h < 2; h++) {
                        float* d = acc[mt][ntp * 2 + h];
                        mma16816(d, ahi[mt], &bhi[ntp][h * 2]);
                        mma16816(d, ahi[mt], &blo[ntp][h * 2]);
                        mma16816(d, alo[mt], &bhi[ntp][h * 2]);
                    }
        }
        __syncthreads();
    }

#pragma unroll
    for (int mt = 0; mt < 4; mt++) {
        int r0 = mBase + wm * 64 + mt * 16 + (lane >> 2);
#pragma unroll
        for (int nt = 0; nt < 4; nt++) {
            int col = nBase + wn * 32 + nt * 8 + (lane & 3) * 2;
            float bx = bias[col], by = bias[col + 1];
            float* d = acc[mt][nt];
#pragma unroll
            for (int hrow = 0; hrow < 2; hrow++) {
                int r = r0 + hrow * 8;
                size_t off = (size_t)r * N + col;
                float vx = d[hrow * 2 + 0] + bx;
                float vy = d[hrow * 2 + 1] + by;
                if (RES) {
                    float2 rv = *(const float2*)(res + off);
                    vx += rv.x; vy += rv.y;
                }
                if (RELU) { vx = fmaxf(vx, 0.f); vy = fmaxf(vy, 0.f); }
                if (OUTF) {
                    float2 o; o.x = vx; o.y = vy;
                    *(float2*)(C + off) = o;
                }
                if (OUTB) {
                    uint32_t lo;
                    uint32_t hi = packsplit(vx, vy, lo);
                    *(uint32_t*)(Ch + off) = hi;
                    *(uint32_t*)(Cl + off) = lo;
                }
            }
        }
    }
}

// ---------------------------------------------------------------------------
// HMMA causal flash attention. CTA: 64 q-rows x one (b,h); 4 warps.
// 64-kpos tiles, 2-stage cp.async (73728 B -> 3 CTAs/SM).
// ---------------------------------------------------------------------------
#define ATT_PITCH 144
#define ATT_TILE  (64 * ATT_PITCH)         // 9216 B
#define ATT_STAGE (4 * ATT_TILE)           // 36864 B
#define ATT_SMEM  (2 * ATT_STAGE)          // 73728 B

__global__ void __launch_bounds__(128)
attn_tc(const __nv_bfloat16* __restrict__ QKVh, const __nv_bfloat16* __restrict__ QKVl,
        __nv_bfloat16* __restrict__ OH, __nv_bfloat16* __restrict__ OL)
{
    extern __shared__ char sm[];
    uint32_t smBase = smem_u32(sm);

    int b = blockIdx.z, h = blockIdx.y;
    int qb = gridDim.x - 1 - blockIdx.x;     // heavy blocks first
    int tid = threadIdx.x, w = tid >> 5, lane = tid & 31;

    size_t rowBase = (size_t)b * SEQ * LDQKV;
    const __nv_bfloat16* Qh = QKVh + rowBase + h * HDIM;
    const __nv_bfloat16* Ql = QKVl + rowBase + h * HDIM;
    const __nv_bfloat16* Kh = QKVh + rowBase + D_MODEL + h * HDIM;
    const __nv_bfloat16* Kl = QKVl + rowBase + D_MODEL + h * HDIM;
    const __nv_bfloat16* Vh = QKVh + rowBase + 2 * D_MODEL + h * HDIM;
    const __nv_bfloat16* Vl = QKVl + rowBase + 2 * D_MODEL + h * HDIM;

    uint32_t qhi[4][4], qlo[4][4];
    {
        __nv_bfloat162 sc = __floats2bfloat162_rn(0.125f, 0.125f);
        int rA = qb * 64 + w * 16 + (lane >> 2);
        int cA = (lane & 3) * 2;
#pragma unroll
        for (int kt = 0; kt < 4; kt++) {
            int c0 = kt * 16 + cA;
            const __nv_bfloat16* p00 = Qh + (size_t)rA * LDQKV + c0;
            const __nv_bfloat16* p10 = Qh + (size_t)(rA + 8) * LDQKV + c0;
            const __nv_bfloat16* l00 = Ql + (size_t)rA * LDQKV + c0;
            const __nv_bfloat16* l10 = Ql + (size_t)(rA + 8) * LDQKV + c0;
            __nv_bfloat162 v;
            v = __hmul2(*(const __nv_bfloat162*)(p00),     sc); qhi[kt][0] = *(uint32_t*)&v;
            v = __hmul2(*(const __nv_bfloat162*)(p10),     sc); qhi[kt][1] = *(uint32_t*)&v;
            v = __hmul2(*(const __nv_bfloat162*)(p00 + 8), sc); qhi[kt][2] = *(uint32_t*)&v;
            v = __hmul2(*(const __nv_bfloat162*)(p10 + 8), sc); qhi[kt][3] = *(uint32_t*)&v;
            v = __hmul2(*(const __nv_bfloat162*)(l00),     sc); qlo[kt][0] = *(uint32_t*)&v;
            v = __hmul2(*(const __nv_bfloat162*)(l10),     sc); qlo[kt][1] = *(uint32_t*)&v;
            v = __hmul2(*(const __nv_bfloat162*)(l00 + 8), sc); qlo[kt][2] = *(uint32_t*)&v;
            v = __hmul2(*(const __nv_bfloat162*)(l10 + 8), sc); qlo[kt][3] = *(uint32_t*)&v;
        }
    }

    auto issueTile = [&](int t) {
        uint32_t st = smBase + (t & 1) * ATT_STAGE;
        int k0 = t * 64;
#pragma unroll
        for (int i = 0; i < 4; i++) {
            int chunk = tid + i * 128;        // 0..511
            int r = chunk >> 3, seg = chunk & 7;
            size_t go = (size_t)(k0 + r) * LDQKV;
            uint32_t so = r * ATT_PITCH + seg * 16;
            cpasync16(st + 0 * ATT_TILE + so, (const char*)(Kh + go) + seg * 16);
            cpasync16(st + 1 * ATT_TILE + so, (const char*)(Kl + go) + seg * 16);
            cpasync16(st + 2 * ATT_TILE + so, (const char*)(Vh + go) + seg * 16);
            cpasync16(st + 3 * ATT_TILE + so, (const char*)(Vl + go) + seg * 16);
        }
    };

    float o[8][4];
#pragma unroll
    for (int i = 0; i < 8; i++)
#pragma unroll
        for (int j = 0; j < 4; j++) o[i][j] = 0.f;
    float m0 = -1e30f, m1 = -1e30f, l0 = 0.f, l1 = 0.f;

    int ntb = qb + 1;
    int laneNB = (lane >> 4) * 8 + (lane & 7);
    int laneKB = ((lane >> 3) & 1) * 8;
    int vr = ((lane >> 3) & 1) * 8 + (lane & 7);
    int vc = ((lane >> 4) & 1) * 8;

    issueTile(0); CP_COMMIT();
    if (ntb > 1) { issueTile(1); CP_COMMIT(); }

    for (int t = 0; t < ntb; t++) {
        if (t + 1 < ntb) { CP_WAIT(1); } else { CP_WAIT(0); }
        __syncthreads();
        uint32_t st = smBase + (t & 1) * ATT_STAGE;

        // ---- S = Q K^T (pre-scaled) ----------------------------------------
        float s[8][4];
#pragma unroll
        for (int i = 0; i < 8; i++)
#pragma unroll
            for (int j = 0; j < 4; j++) s[i][j] = 0.f;

#pragma unroll
        for (int kt = 0; kt < 4; kt++) {
#pragma unroll
            for (int ng = 0; ng < 4; ng++) {
                uint32_t kh[4], kl[4];
                uint32_t ka = st + (ng * 16 + laneNB) * ATT_PITCH + (kt * 16 + laneKB) * 2;
                ldsm_x4(ka, kh);
                ldsm_x4(ka + ATT_TILE, kl);
#pragma unroll
                for (int hf = 0; hf < 2; hf++) {
                    float* d = s[ng * 2 + hf];
                    mma16816(d, qhi[kt], &kh[hf * 2]);
                    mma16816(d, qhi[kt], &kl[hf * 2]);
                    mma16816(d, qlo[kt], &kh[hf * 2]);
                }
            }
        }

        // ---- causal mask (diagonal tile only) ------------------------------
        if (t == qb) {
            int rg0 = qb * 64 + w * 16 + (lane >> 2);
            int rg1 = rg0 + 8;
#pragma unroll
            for (int nt = 0; nt < 8; nt++) {
                int c0 = t * 64 + nt * 8 + (lane & 3) * 2;
                if (c0     > rg0) s[nt][0] = -1e30f;
                if (c0 + 1 > rg0) s[nt][1] = -1e30f;
                if (c0     > rg1) s[nt][2] = -1e30f;
                if (c0 + 1 > rg1) s[nt][3] = -1e30f;
            }
        }

        // ---- online softmax -------------------------------------------------
        float mx0 = m0, mx1 = m1;
#pragma unroll
        for (int nt = 0; nt < 8; nt++) {
            mx0 = fmaxf(mx0, fmaxf(s[nt][0], s[nt][1]));
            mx1 = fmaxf(mx1, fmaxf(s[nt][2], s[nt][3]));
        }
        mx0 = fmaxf(mx0, __shfl_xor_sync(0xffffffffu, mx0, 1));
        mx0 = fmaxf(mx0, __shfl_xor_sync(0xffffffffu, mx0, 2));
        mx1 = fmaxf(mx1, __shfl_xor_sync(0xffffffffu, mx1, 1));
        mx1 = fmaxf(mx1, __shfl_xor_sync(0xffffffffu, mx1, 2));
        float f0 = __expf(m0 - mx0), f1 = __expf(m1 - mx1);
        m0 = mx0; m1 = mx1;

        float rs0 = 0.f, rs1 = 0.f;
#pragma unroll
        for (int nt = 0; nt < 8; nt++) {
            s[nt][0] = __expf(s[nt][0] - mx0);
            s[nt][1] = __expf(s[nt][1] - mx0);
            s[nt][2] = __expf(s[nt][2] - mx1);
            s[nt][3] = __expf(s[nt][3] - mx1);
            rs0 += s[nt][0] + s[nt][1];
            rs1 += s[nt][2] + s[nt][3];
        }
        rs0 += __shfl_xor_sync(0xffffffffu, rs0, 1);
        rs0 += __shfl_xor_sync(0xffffffffu, rs0, 2);
        rs1 += __shfl_xor_sync(0xffffffffu, rs1, 1);
        rs1 += __shfl_xor_sync(0xffffffffu, rs1, 2);
        l0 = l0 * f0 + rs0;
        l1 = l1 * f1 + rs1;

#pragma unroll
        for (int nt = 0; nt < 8; nt++) {
            o[nt][0] *= f0; o[nt][1] *= f0;
            o[nt][2] *= f1; o[nt][3] *= f1;
        }

        // ---- P fragments (hi/lo) -------------------------------------------
        uint32_t phi[4][4], plo[4][4];
#pragma unroll
        for (int kt = 0; kt < 4; kt++) {
            phi[kt][0] = packsplit(s[2*kt][0],   s[2*kt][1],   plo[kt][0]);
            phi[kt][1] = packsplit(s[2*kt][2],   s[2*kt][3],   plo[kt][1]);
            phi[kt][2] = packsplit(s[2*kt+1][0], s[2*kt+1][1], plo[kt][2]);
            phi[kt][3] = packsplit(s[2*kt+1][2], s[2*kt+1][3], plo[kt][3]);
        }

        // ---- O += P V -------------------------------------------------------
#pragma unroll
        for (int kt = 0; kt < 4; kt++) {
#pragma unroll
            for (int dg = 0; dg < 4; dg++) {
                uint32_t vh[4], vl[4];
                uint32_t va = st + 2 * ATT_TILE + (kt * 16 + vr) * ATT_PITCH + (dg * 16 + vc) * 2;
                ldsm_x4_t(va, vh);
                ldsm_x4_t(va + ATT_TILE, vl);
#pragma unroll
                for (int hf = 0; hf < 2; hf++) {
                    float* d = o[dg * 2 + hf];
                    mma16816(d, phi[kt], &vh[hf * 2]);
                    mma16816(d, phi[kt], &vl[hf * 2]);
                    mma16816(d, plo[kt], &vh[hf * 2]);
                }
            }
        }
        __syncthreads();
        if (t + 2 < ntb) { issueTile(t + 2); CP_COMMIT(); }
    }

    // ---- normalize + store bf16 hi/lo --------------------------------------
    float inv0 = 1.f / l0, inv1 = 1.f / l1;
    int ro0 = qb * 64 + w * 16 + (lane >> 2);
    size_t ob0 = ((size_t)(b * SEQ) + ro0) * D_MODEL + h * HDIM;
    size_t ob1 = ob0 + 8 * (size_t)D_MODEL;
#pragma unroll
    for (int nt = 0; nt < 8; nt++) {
        int c = nt * 8 + (lane & 3) * 2;
        uint32_t lo;
        uint32_t hi = packsplit(o[nt][0] * inv0, o[nt][1] * inv0, lo);
        *(uint32_t*)(OH + ob0 + c) = hi;
        *(uint32_t*)(OL + ob0 + c) = lo;
        hi = packsplit(o[nt][2] * inv1, o[nt][3] * inv1, lo);
        *(uint32_t*)(OH + ob1 + c) = hi;
        *(uint32_t*)(OL + ob1 + c) = lo;
    }
}

// ---------------------------------------------------------------------------
// Launch
// ---------------------------------------------------------------------------
extern "C" void kernel_launch(void* const* d_in, const int* in_sizes, int n_in,
                              void* d_out, int out_size)
{
    (void)in_sizes; (void)n_in; (void)out_size;
    const float* x     = (const float*)d_in[0];
    const float* wq    = (const float*)d_in[1];
    const float* bq    = (const float*)d_in[2];
    const float* wk    = (const float*)d_in[3];
    const float* bk    = (const float*)d_in[4];
    const float* wv    = (const float*)d_in[5];
    const float* bv    = (const float*)d_in[6];
    const float* wo    = (const float*)d_in[7];
    const float* bo    = (const float*)d_in[8];
    const float* w1    = (const float*)d_in[9];
    const float* b1    = (const float*)d_in[10];
    const float* w2    = (const float*)d_in[11];
    const float* b2    = (const float*)d_in[12];
    const float* ln1_g = (const float*)d_in[13];
    const float* ln1_b = (const float*)d_in[14];
    const float* ln2_g = (const float*)d_in[15];
    const float* ln2_b = (const float*)d_in[16];
    float* out = (float*)d_out;

    float *x1, *bqkv;
    __nv_bfloat16 *ln1h, *ln1l, *qkvh, *qkvl, *attnh, *attnl, *ln2h, *ln2l, *ff1h, *ff1l;
    __nv_bfloat16 *wqkvth, *wqkvtl, *woth, *wotl, *w1th, *w1tl, *w2th, *w2tl;
    cudaGetSymbolAddress((void**)&x1,   g_x1);
    cudaGetSymbolAddress((void**)&bqkv, g_bqkv);
    cudaGetSymbolAddress((void**)&ln1h, g_ln1h);  cudaGetSymbolAddress((void**)&ln1l, g_ln1l);
    cudaGetSymbolAddress((void**)&qkvh, g_qkvh);  cudaGetSymbolAddress((void**)&qkvl, g_qkvl);
    cudaGetSymbolAddress((void**)&attnh,g_attnh); cudaGetSymbolAddress((void**)&attnl,g_attnl);
    cudaGetSymbolAddress((void**)&ln2h, g_ln2h);  cudaGetSymbolAddress((void**)&ln2l, g_ln2l);
    cudaGetSymbolAddress((void**)&ff1h, g_ff1h);  cudaGetSymbolAddress((void**)&ff1l, g_ff1l);
    cudaGetSymbolAddress((void**)&wqkvth, g_wqkvth); cudaGetSymbolAddress((void**)&wqkvtl, g_wqkvtl);
    cudaGetSymbolAddress((void**)&woth, g_woth);  cudaGetSymbolAddress((void**)&wotl, g_wotl);
    cudaGetSymbolAddress((void**)&w1th, g_w1th);  cudaGetSymbolAddress((void**)&w1tl, g_w1tl);
    cudaGetSymbolAddress((void**)&w2th, g_w2th);  cudaGetSymbolAddress((void**)&w2tl, g_w2tl);

    cudaFuncSetAttribute(gemm_tc<false,false,false,true>,
                         cudaFuncAttributeMaxDynamicSharedMemorySize, GEMM_SMEM);
    cudaFuncSetAttribute(gemm_tc<false,true,true,false>,
                         cudaFuncAttributeMaxDynamicSharedMemorySize, GEMM_SMEM);
    cudaFuncSetAttribute(gemm_tc<true,false,false,true>,
                         cudaFuncAttributeMaxDynamicSharedMemorySize, GEMM_SMEM);
    cudaFuncSetAttribute(attn_tc,
                         cudaFuncAttributeMaxDynamicSharedMemorySize, ATT_SMEM);

    // fused QKV bias
    cudaMemcpyAsync(bqkv,             bq, D_MODEL * sizeof(float), cudaMemcpyDeviceToDevice);
    cudaMemcpyAsync(bqkv + D_MODEL,   bk, D_MODEL * sizeof(float), cudaMemcpyDeviceToDevice);
    cudaMemcpyAsync(bqkv + 2*D_MODEL, bv, D_MODEL * sizeof(float), cudaMemcpyDeviceToDevice);

    // all weight transposes + hi/lo splits in one launch (6912 tiles)
    wconv_all<<<6912, dim3(32, 8)>>>(wq, wk, wv, wo, w1, w2,
                                     wqkvth, wqkvtl, woth, wotl,
                                     w1th, w1tl, w2th, w2tl);

    // 1) LN1 -> bf16 hi/lo
    ln_kernel<<<MROWS, 256>>>(x, ln1_g, ln1_b, ln1h, ln1l);
    // 2) fused QKV projection -> bf16 hi/lo [4096, 2304]
    gemm_tc<false,false,false,true><<<dim3(LDQKV/128, MROWS/128), 256, GEMM_SMEM>>>(
        ln1h, ln1l, wqkvth, wqkvtl, bqkv, nullptr, nullptr, qkvh, qkvl, MROWS, LDQKV, D_MODEL);
    // 3) HMMA causal flash attention -> bf16 hi/lo
    attn_tc<<<dim3(SEQ/64, NHEAD, BATCH), 128, ATT_SMEM>>>(qkvh, qkvl, attnh, attnl);
    // 4) O projection + residual (fp32 x1)
    gemm_tc<false,true,true,false><<<dim3(D_MODEL/128, MROWS/128), 256, GEMM_SMEM>>>(
        attnh, attnl, woth, wotl, bo, x, x1, nullptr, nullptr, MROWS, D_MODEL, D_MODEL);
    // 5) LN2 -> bf16 hi/lo
    ln_kernel<<<MROWS, 256>>>(x1, ln2_g, ln2_b, ln2h, ln2l);
    // 6) FFN up + ReLU -> bf16 hi/lo
    gemm_tc<true,false,false,true><<<dim3(D_FF/128, MROWS/128), 256, GEMM_SMEM>>>(
        ln2h, ln2l, w1th, w1tl, b1, nullptr, nullptr, ff1h, ff1l, MROWS, D_FF, D_MODEL);
    // 7) FFN down + residual -> output (fp32)
    gemm_tc<false,true,true,false><<<dim3(D_MODEL/128, MROWS/128), 256, GEMM_SMEM>>>(
        ff1h, ff1l, w2th, w2tl, b2, x1, out, nullptr, nullptr, MROWS, D_MODEL, D_FF);
}

// round 16
// speedup vs baseline: 1.1472x; 1.0485x over previous
#include <cuda_runtime.h>
#include <cuda_bf16.h>
#include <cstdint>

// ---------------------------------------------------------------------------
// TransformerBlock: B=2, S=2048, D=768, H=12, Hd=64, D_FF=3072, fp32 I/O.
// Round 12: revert GEMM to proven 128x64/2-stage; attention widened to
//           256 threads / 128 q-rows per CTA (halved K/V traffic, more warps).
// ---------------------------------------------------------------------------

#define D_MODEL 768
#define D_FF    3072
#define SEQ     2048
#define BATCH   2
#define NHEAD   12
#define HDIM    64
#define MROWS   (BATCH * SEQ)   // 4096
#define LDQKV   (3 * D_MODEL)   // 2304

// ---------------- scratch (static device globals; no allocation) -----------
__device__ float g_x1  [MROWS * D_MODEL];
__device__ float g_bqkv[LDQKV];

__device__ __nv_bfloat16 g_ln1h[MROWS * D_MODEL], g_ln1l[MROWS * D_MODEL];
__device__ __nv_bfloat16 g_qkvh[MROWS * LDQKV],   g_qkvl[MROWS * LDQKV];
__device__ __nv_bfloat16 g_attnh[MROWS * D_MODEL], g_attnl[MROWS * D_MODEL];
__device__ __nv_bfloat16 g_ln2h[MROWS * D_MODEL], g_ln2l[MROWS * D_MODEL];
__device__ __nv_bfloat16 g_ff1h[MROWS * D_FF],   g_ff1l[MROWS * D_FF];

__device__ __nv_bfloat16 g_wqkvth[LDQKV * D_MODEL], g_wqkvtl[LDQKV * D_MODEL];
__device__ __nv_bfloat16 g_woth[D_MODEL * D_MODEL], g_wotl[D_MODEL * D_MODEL];
__device__ __nv_bfloat16 g_w1th[D_FF * D_MODEL],    g_w1tl[D_FF * D_MODEL];
__device__ __nv_bfloat16 g_w2th[D_MODEL * D_FF],    g_w2tl[D_MODEL * D_FF];

// ---------------------------------------------------------------------------
// PTX helpers
// ---------------------------------------------------------------------------
__device__ __forceinline__ uint32_t smem_u32(const void* p) {
    uint32_t a;
    asm("{ .reg .u64 t; cvta.to.shared.u64 t, %1; cvt.u32.u64 %0, t; }"
        : "=r"(a) : "l"(p));
    return a;
}
__device__ __forceinline__ void ldsm_x4(uint32_t addr, uint32_t* r) {
    asm volatile("ldmatrix.sync.aligned.m8n8.x4.shared.b16 {%0,%1,%2,%3}, [%4];"
        : "=r"(r[0]), "=r"(r[1]), "=r"(r[2]), "=r"(r[3]) : "r"(addr));
}
__device__ __forceinline__ void ldsm_x4_t(uint32_t addr, uint32_t* r) {
    asm volatile("ldmatrix.sync.aligned.m8n8.x4.trans.shared.b16 {%0,%1,%2,%3}, [%4];"
        : "=r"(r[0]), "=r"(r[1]), "=r"(r[2]), "=r"(r[3]) : "r"(addr));
}
__device__ __forceinline__ void mma16816(float* d, const uint32_t* a, const uint32_t* b) {
    asm volatile("mma.sync.aligned.m16n8k16.row.col.f32.bf16.bf16.f32 "
        "{%0,%1,%2,%3}, {%4,%5,%6,%7}, {%8,%9}, {%0,%1,%2,%3};"
        : "+f"(d[0]), "+f"(d[1]), "+f"(d[2]), "+f"(d[3])
        : "r"(a[0]), "r"(a[1]), "r"(a[2]), "r"(a[3]), "r"(b[0]), "r"(b[1]));
}
__device__ __forceinline__ void cpasync16(uint32_t dst, const void* src) {
    asm volatile("cp.async.cg.shared.global [%0], [%1], 16;" :: "r"(dst), "l"(src));
}
#define CP_COMMIT()  asm volatile("cp.async.commit_group;" ::: "memory")
#define CP_WAIT(n)   asm volatile("cp.async.wait_group %0;" :: "n"(n) : "memory")

__device__ __forceinline__ uint32_t packsplit(float x, float y, uint32_t& lo) {
    __nv_bfloat162 h = __floats2bfloat162_rn(x, y);
    float hx = __bfloat162float(h.x), hy = __bfloat162float(h.y);
    __nv_bfloat162 l = __floats2bfloat162_rn(x - hx, y - hy);
    lo = *(uint32_t*)&l;
    return *(uint32_t*)&h;
}

// ---------------------------------------------------------------------------
// LayerNorm -> bf16 hi/lo
// ---------------------------------------------------------------------------
__global__ void __launch_bounds__(256)
ln_kernel(const float* __restrict__ x, const float* __restrict__ g,
          const float* __restrict__ b, __nv_bfloat16* __restrict__ outH,
          __nv_bfloat16* __restrict__ outL)
{
    int row = blockIdx.x;
    const float* xr = x + (size_t)row * D_MODEL;
    int tid = threadIdx.x;
    float v[3];
    float s = 0.f, s2 = 0.f;
#pragma unroll
    for (int i = 0; i < 3; i++) {
        v[i] = xr[tid + i * 256];
        s  += v[i];
        s2 += v[i] * v[i];
    }
    int lane = tid & 31, warp = tid >> 5;
#pragma unroll
    for (int o = 16; o; o >>= 1) {
        s  += __shfl_xor_sync(0xffffffffu, s,  o);
        s2 += __shfl_xor_sync(0xffffffffu, s2, o);
    }
    __shared__ float rs[8], rs2[8], mu_s, rstd_s;
    if (lane == 0) { rs[warp] = s; rs2[warp] = s2; }
    __syncthreads();
    if (tid == 0) {
        float a = 0.f, c = 0.f;
#pragma unroll
        for (int i = 0; i < 8; i++) { a += rs[i]; c += rs2[i]; }
        float mu  = a * (1.f / D_MODEL);
        float var = c * (1.f / D_MODEL) - mu * mu;
        mu_s = mu;
        rstd_s = rsqrtf(var + 1e-5f);
    }
    __syncthreads();
    float mu = mu_s, rstd = rstd_s;
#pragma unroll
    for (int i = 0; i < 3; i++) {
        int d = tid + i * 256;
        float y = (v[i] - mu) * rstd * g[d] + b[d];
        __nv_bfloat16 h = __float2bfloat16(y);
        float lo = y - __bfloat162float(h);
        size_t o = (size_t)row * D_MODEL + d;
        outH[o] = h;
        outL[o] = __float2bfloat16(lo);
    }
}

// ---------------------------------------------------------------------------
// Single-launch weight transpose + hi/lo split for all 6 weights.
// ---------------------------------------------------------------------------
__global__ void __launch_bounds__(256)
wconv_all(const float* __restrict__ wq, const float* __restrict__ wk,
          const float* __restrict__ wv, const float* __restrict__ wo,
          const float* __restrict__ w1, const float* __restrict__ w2,
          __nv_bfloat16* __restrict__ qkvh, __nv_bfloat16* __restrict__ qkvl,
          __nv_bfloat16* __restrict__ woh,  __nv_bfloat16* __restrict__ wol,
          __nv_bfloat16* __restrict__ w1h,  __nv_bfloat16* __restrict__ w1l,
          __nv_bfloat16* __restrict__ w2h,  __nv_bfloat16* __restrict__ w2l)
{
    int bid = blockIdx.x;
    const float* W;
    __nv_bfloat16 *TH, *TL;
    int K, N, tile;
    if (bid < 2304) {
        int wsel = bid / 576;
        tile = bid - wsel * 576;
        K = 768; N = 768;
        if (wsel == 0)      { W = wq; TH = qkvh;                     TL = qkvl; }
        else if (wsel == 1) { W = wk; TH = qkvh + D_MODEL * D_MODEL; TL = qkvl + D_MODEL * D_MODEL; }
        else if (wsel == 2) { W = wv; TH = qkvh + 2*D_MODEL*D_MODEL; TL = qkvl + 2*D_MODEL*D_MODEL; }
        else                { W = wo; TH = woh;                      TL = wol; }
    } else if (bid < 4608) {
        tile = bid - 2304; K = 768; N = 3072; W = w1; TH = w1h; TL = w1l;
    } else {
        tile = bid - 4608; K = 3072; N = 768; W = w2; TH = w2h; TL = w2l;
    }
    int tilesX = N >> 5;
    int n0 = (tile % tilesX) * 32;
    int k0 = (tile / tilesX) * 32;

    __shared__ float t[32][33];
    int x = threadIdx.x, y = threadIdx.y;
#pragma unroll
    for (int i = y; i < 32; i += 8)
        t[i][x] = W[(size_t)(k0 + i) * N + n0 + x];
    __syncthreads();
#pragma unroll
    for (int i = y; i < 32; i += 8) {
        float v = t[x][i];          // = W[k0+x][n0+i]
        __nv_bfloat16 h = __float2bfloat16(v);
        float lo = v - __bfloat162float(h);
        size_t o = (size_t)(n0 + i) * K + k0 + x;
        TH[o] = h;
        TL[o] = __float2bfloat16(lo);
    }
}

// ---------------------------------------------------------------------------
// HMMA bf16x3 GEMM: C[M,N] = A[M,K] x B[N,K]^T  (proven round-5 config)
// CTA tile 128x64, 8 warps x (32m x 32n), KC=32, 2-stage cp.async pipeline.
// SMEM 61440 B -> 3 CTAs/SM.
// ---------------------------------------------------------------------------
#define KC      32
#define A_HI    0
#define A_LO    (128 * 80)                  // 10240 B
#define B_HI    (2 * 128 * 80)              // 20480 B
#define B_LO    (B_HI + 64 * 80)            // 25600 B
#define STAGE_B (B_LO + 64 * 80)            // 30720 B per stage
#define GEMM_SMEM (2 * STAGE_B)             // 61440 B

template<bool RELU, bool RES, bool OUTF, bool OUTB>
__global__ void __launch_bounds__(256)
gemm_tc(const __nv_bfloat16* __restrict__ Ah, const __nv_bfloat16* __restrict__ Al,
        const __nv_bfloat16* __restrict__ Bh, const __nv_bfloat16* __restrict__ Bl,
        const float* __restrict__ bias, const float* __restrict__ res,
        float* __restrict__ C, __nv_bfloat16* __restrict__ Ch, __nv_bfloat16* __restrict__ Cl,
        int M, int N, int K)
{
    extern __shared__ char sm[];
    uint32_t smBase = smem_u32(sm);

    int tid = threadIdx.x;
    int wid = tid >> 5, lane = tid & 31;
    int mBase = blockIdx.y * 128;
    int nBase = blockIdx.x * 64;

    int aRow0 = tid >> 2,  aSeg0 = tid & 3;
    int aRow1 = (tid + 256) >> 2, aSeg1 = (tid + 256) & 3;
    int bRow = tid >> 2, bSeg = tid & 3;

    const char* gAh = (const char*)(Ah + (size_t)(mBase) * K);
    const char* gAl = (const char*)(Al + (size_t)(mBase) * K);
    const char* gBh = (const char*)(Bh + (size_t)(nBase) * K);
    const char* gBl = (const char*)(Bl + (size_t)(nBase) * K);

    int nch = K / KC;

    auto issue = [&](int c) {
        uint32_t st = smBase + (c & 1) * STAGE_B;
        size_t kOff = (size_t)c * KC * 2;
        cpasync16(st + A_HI + aRow0 * 80 + aSeg0 * 16, gAh + (size_t)aRow0 * K * 2 + kOff + aSeg0 * 16);
        cpasync16(st + A_HI + aRow1 * 80 + aSeg1 * 16, gAh + (size_t)aRow1 * K * 2 + kOff + aSeg1 * 16);
        cpasync16(st + A_LO + aRow0 * 80 + aSeg0 * 16, gAl + (size_t)aRow0 * K * 2 + kOff + aSeg0 * 16);
        cpasync16(st + A_LO + aRow1 * 80 + aSeg1 * 16, gAl + (size_t)aRow1 * K * 2 + kOff + aSeg1 * 16);
        cpasync16(st + B_HI + bRow * 80 + bSeg * 16, gBh + (size_t)bRow * K * 2 + kOff + bSeg * 16);
        cpasync16(st + B_LO + bRow * 80 + bSeg * 16, gBl + (size_t)bRow * K * 2 + kOff + bSeg * 16);
    };

    float acc[2][4][4];
#pragma unroll
    for (int i = 0; i < 2; i++)
#pragma unroll
        for (int j = 0; j < 4; j++)
#pragma unroll
            for (int q = 0; q < 4; q++) acc[i][j][q] = 0.f;

    int wm = wid & 3;
    int wn = wid >> 2;

    int laneM = (lane & 7) + ((lane >> 3) & 1) * 8;
    int laneKA = (lane >> 4) * 8;
    int laneNB = (lane >> 4) * 8 + (lane & 7);
    int laneKB = ((lane >> 3) & 1) * 8;

    issue(0);
    CP_COMMIT();

    for (int c = 0; c < nch; c++) {
        if (c + 1 < nch) {
            issue(c + 1);
            CP_COMMIT();
            CP_WAIT(1);
        } else {
            CP_WAIT(0);
        }
        __syncthreads();

        uint32_t st = smBase + (c & 1) * STAGE_B;
#pragma unroll
        for (int ks = 0; ks < KC; ks += 16) {
            uint32_t ahi[2][4], alo[2][4], bhi[2][4], blo[2][4];
#pragma unroll
            for (int mt = 0; mt < 2; mt++) {
                int row = wm * 32 + mt * 16 + laneM;
                uint32_t col = (uint32_t)(ks + laneKA) * 2;
                ldsm_x4(st + A_HI + row * 80 + col, ahi[mt]);
                ldsm_x4(st + A_LO + row * 80 + col, alo[mt]);
            }
#pragma unroll
            for (int ntp = 0; ntp < 2; ntp++) {
                int n = wn * 32 + ntp * 16 + laneNB;
                uint32_t col = (uint32_t)(ks + laneKB) * 2;
                ldsm_x4(st + B_HI + n * 80 + col, bhi[ntp]);
                ldsm_x4(st + B_LO + n * 80 + col, blo[ntp]);
            }
#pragma unroll
            for (int mt = 0; mt < 2; mt++)
#pragma unroll
                for (int ntp = 0; ntp < 2; ntp++)
#pragma unroll
                    for (int h = 0; h < 2; h++) {
                        float* d = acc[mt][ntp * 2 + h];
                        mma16816(d, ahi[mt], &bhi[ntp][h * 2]);
                        mma16816(d, ahi[mt], &blo[ntp][h * 2]);
                        mma16816(d, alo[mt], &bhi[ntp][h * 2]);
                    }
        }
        __syncthreads();
    }

#pragma unroll
    for (int mt = 0; mt < 2; mt++) {
        int r0 = mBase + wm * 32 + mt * 16 + (lane >> 2);
#pragma unroll
        for (int nt = 0; nt < 4; nt++) {
            int col = nBase + wn * 32 + nt * 8 + (lane & 3) * 2;
            float bx = bias[col], by = bias[col + 1];
            float* d = acc[mt][nt];
#pragma unroll
            for (int hrow = 0; hrow < 2; hrow++) {
                int r = r0 + hrow * 8;
                size_t off = (size_t)r * N + col;
                float vx = d[hrow * 2 + 0] + bx;
                float vy = d[hrow * 2 + 1] + by;
                if (RES) {
                    float2 rv = *(const float2*)(res + off);
                    vx += rv.x; vy += rv.y;
                }
                if (RELU) { vx = fmaxf(vx, 0.f); vy = fmaxf(vy, 0.f); }
                if (OUTF) {
                    float2 o; o.x = vx; o.y = vy;
                    *(float2*)(C + off) = o;
                }
                if (OUTB) {
                    uint32_t lo;
                    uint32_t hi = packsplit(vx, vy, lo);
                    *(uint32_t*)(Ch + off) = hi;
                    *(uint32_t*)(Cl + off) = lo;
                }
            }
        }
    }
}

// ---------------------------------------------------------------------------
// HMMA causal flash attention. CTA: 128 q-rows x one (b,h); 8 warps x 16 rows.
// 64-kpos K/V tiles (shared by all 8 warps), 2-stage cp.async.
// SMEM 73728 B, regs capped for 2 CTAs/SM -> 16 warps/SM.
// ---------------------------------------------------------------------------
#define ATT_PITCH 144
#define ATT_TILE  (64 * ATT_PITCH)         // 9216 B
#define ATT_STAGE (4 * ATT_TILE)           // 36864 B
#define ATT_SMEM  (2 * ATT_STAGE)          // 73728 B
#define QROWS     128

__global__ void __launch_bounds__(256, 2)
attn_tc(const __nv_bfloat16* __restrict__ QKVh, const __nv_bfloat16* __restrict__ QKVl,
        __nv_bfloat16* __restrict__ OH, __nv_bfloat16* __restrict__ OL)
{
    extern __shared__ char sm[];
    uint32_t smBase = smem_u32(sm);

    int b = blockIdx.z, h = blockIdx.y;
    int qb = gridDim.x - 1 - blockIdx.x;     // heavy blocks first
    int tid = threadIdx.x, w = tid >> 5, lane = tid & 31;

    size_t rowBase = (size_t)b * SEQ * LDQKV;
    const __nv_bfloat16* Qh = QKVh + rowBase + h * HDIM;
    const __nv_bfloat16* Ql = QKVl + rowBase + h * HDIM;
    const __nv_bfloat16* Kh = QKVh + rowBase + D_MODEL + h * HDIM;
    const __nv_bfloat16* Kl = QKVl + rowBase + D_MODEL + h * HDIM;
    const __nv_bfloat16* Vh = QKVh + rowBase + 2 * D_MODEL + h * HDIM;
    const __nv_bfloat16* Vl = QKVl + rowBase + 2 * D_MODEL + h * HDIM;

    int wRow = qb * QROWS + w * 16;          // first q-row of this warp

    // ---- Q fragments (pre-scaled by 1/8, exact) ----------------------------
    uint32_t qhi[4][4], qlo[4][4];
    {
        __nv_bfloat162 sc = __floats2bfloat162_rn(0.125f, 0.125f);
        int rA = wRow + (lane >> 2);
        int cA = (lane & 3) * 2;
#pragma unroll
        for (int kt = 0; kt < 4; kt++) {
            int c0 = kt * 16 + cA;
            const __nv_bfloat16* p00 = Qh + (size_t)rA * LDQKV + c0;
            const __nv_bfloat16* p10 = Qh + (size_t)(rA + 8) * LDQKV + c0;
            const __nv_bfloat16* l00 = Ql + (size_t)rA * LDQKV + c0;
            const __nv_bfloat16* l10 = Ql + (size_t)(rA + 8) * LDQKV + c0;
            __nv_bfloat162 v;
            v = __hmul2(*(const __nv_bfloat162*)(p00),     sc); qhi[kt][0] = *(uint32_t*)&v;
            v = __hmul2(*(const __nv_bfloat162*)(p10),     sc); qhi[kt][1] = *(uint32_t*)&v;
            v = __hmul2(*(const __nv_bfloat162*)(p00 + 8), sc); qhi[kt][2] = *(uint32_t*)&v;
            v = __hmul2(*(const __nv_bfloat162*)(p10 + 8), sc); qhi[kt][3] = *(uint32_t*)&v;
            v = __hmul2(*(const __nv_bfloat162*)(l00),     sc); qlo[kt][0] = *(uint32_t*)&v;
            v = __hmul2(*(const __nv_bfloat162*)(l10),     sc); qlo[kt][1] = *(uint32_t*)&v;
            v = __hmul2(*(const __nv_bfloat162*)(l00 + 8), sc); qlo[kt][2] = *(uint32_t*)&v;
            v = __hmul2(*(const __nv_bfloat162*)(l10 + 8), sc); qlo[kt][3] = *(uint32_t*)&v;
        }
    }

    auto issueTile = [&](int t) {
        uint32_t st = smBase + (t & 1) * ATT_STAGE;
        int k0 = t * 64;
#pragma unroll
        for (int i = 0; i < 2; i++) {
            int chunk = tid + i * 256;        // 0..511
            int r = chunk >> 3, seg = chunk & 7;
            size_t go = (size_t)(k0 + r) * LDQKV;
            uint32_t so = r * ATT_PITCH + seg * 16;
            cpasync16(st + 0 * ATT_TILE + so, (const char*)(Kh + go) + seg * 16);
            cpasync16(st + 1 * ATT_TILE + so, (const char*)(Kl + go) + seg * 16);
            cpasync16(st + 2 * ATT_TILE + so, (const char*)(Vh + go) + seg * 16);
            cpasync16(st + 3 * ATT_TILE + so, (const char*)(Vl + go) + seg * 16);
        }
    };

    float o[8][4];
#pragma unroll
    for (int i = 0; i < 8; i++)
#pragma unroll
        for (int j = 0; j < 4; j++) o[i][j] = 0.f;
    float m0 = -1e30f, m1 = -1e30f, l0 = 0.f, l1 = 0.f;

    int ntb = qb * 2 + 2;                    // tiles of 64 kpos for this CTA
    int laneNB = (lane >> 4) * 8 + (lane & 7);
    int laneKB = ((lane >> 3) & 1) * 8;
    int vr = ((lane >> 3) & 1) * 8 + (lane & 7);
    int vc = ((lane >> 4) & 1) * 8;

    issueTile(0); CP_COMMIT();
    if (ntb > 1) { issueTile(1); CP_COMMIT(); }

    for (int t = 0; t < ntb; t++) {
        if (t + 1 < ntb) { CP_WAIT(1); } else { CP_WAIT(0); }
        __syncthreads();
        uint32_t st = smBase + (t & 1) * ATT_STAGE;

        if (t * 64 <= wRow + 15) {           // warp-uniform causal skip
            // ---- S = Q K^T (pre-scaled) ------------------------------------
            float s[8][4];
#pragma unroll
            for (int i = 0; i < 8; i++)
#pragma unroll
                for (int j = 0; j < 4; j++) s[i][j] = 0.f;

#pragma unroll
            for (int kt = 0; kt < 4; kt++) {
#pragma unroll
                for (int ng = 0; ng < 4; ng++) {
                    uint32_t kh[4], kl[4];
                    uint32_t ka = st + (ng * 16 + laneNB) * ATT_PITCH + (kt * 16 + laneKB) * 2;
                    ldsm_x4(ka, kh);
                    ldsm_x4(ka + ATT_TILE, kl);
#pragma unroll
                    for (int hf = 0; hf < 2; hf++) {
                        float* d = s[ng * 2 + hf];
                        mma16816(d, qhi[kt], &kh[hf * 2]);
                        mma16816(d, qhi[kt], &kl[hf * 2]);
                        mma16816(d, qlo[kt], &kh[hf * 2]);
                    }
                }
            }

            // ---- causal mask (tiles overlapping this warp's rows) ----------
            if ((t + 1) * 64 > wRow) {
                int rg0 = wRow + (lane >> 2);
                int rg1 = rg0 + 8;
#pragma unroll
                for (int nt = 0; nt < 8; nt++) {
                    int c0 = t * 64 + nt * 8 + (lane & 3) * 2;
                    if (c0     > rg0) s[nt][0] = -1e30f;
                    if (c0 + 1 > rg0) s[nt][1] = -1e30f;
                    if (c0     > rg1) s[nt][2] = -1e30f;
                    if (c0 + 1 > rg1) s[nt][3] = -1e30f;
                }
            }

            // ---- online softmax --------------------------------------------
            float mx0 = m0, mx1 = m1;
#pragma unroll
            for (int nt = 0; nt < 8; nt++) {
                mx0 = fmaxf(mx0, fmaxf(s[nt][0], s[nt][1]));
                mx1 = fmaxf(mx1, fmaxf(s[nt][2], s[nt][3]));
            }
            mx0 = fmaxf(mx0, __shfl_xor_sync(0xffffffffu, mx0, 1));
            mx0 = fmaxf(mx0, __shfl_xor_sync(0xffffffffu, mx0, 2));
            mx1 = fmaxf(mx1, __shfl_xor_sync(0xffffffffu, mx1, 1));
            mx1 = fmaxf(mx1, __shfl_xor_sync(0xffffffffu, mx1, 2));
            float f0 = __expf(m0 - mx0), f1 = __expf(m1 - mx1);
            m0 = mx0; m1 = mx1;

            float rs0 = 0.f, rs1 = 0.f;
#pragma unroll
            for (int nt = 0; nt < 8; nt++) {
                s[nt][0] = __expf(s[nt][0] - mx0);
                s[nt][1] = __expf(s[nt][1] - mx0);
                s[nt][2] = __expf(s[nt][2] - mx1);
                s[nt][3] = __expf(s[nt][3] - mx1);
                rs0 += s[nt][0] + s[nt][1];
                rs1 += s[nt][2] + s[nt][3];
            }
            rs0 += __shfl_xor_sync(0xffffffffu, rs0, 1);
            rs0 += __shfl_xor_sync(0xffffffffu, rs0, 2);
            rs1 += __shfl_xor_sync(0xffffffffu, rs1, 1);
            rs1 += __shfl_xor_sync(0xffffffffu, rs1, 2);
            l0 = l0 * f0 + rs0;
            l1 = l1 * f1 + rs1;

#pragma unroll
            for (int nt = 0; nt < 8; nt++) {
                o[nt][0] *= f0; o[nt][1] *= f0;
                o[nt][2] *= f1; o[nt][3] *= f1;
            }

            // ---- P fragments (hi/lo) ---------------------------------------
            uint32_t phi[4][4], plo[4][4];
#pragma unroll
            for (int kt = 0; kt < 4; kt++) {
                phi[kt][0] = packsplit(s[2*kt][0],   s[2*kt][1],   plo[kt][0]);
                phi[kt][1] = packsplit(s[2*kt][2],   s[2*kt][3],   plo[kt][1]);
                phi[kt][2] = packsplit(s[2*kt+1][0], s[2*kt+1][1], plo[kt][2]);
                phi[kt][3] = packsplit(s[2*kt+1][2], s[2*kt+1][3], plo[kt][3]);
            }

            // ---- O += P V ---------------------------------------------------
#pragma unroll
            for (int kt = 0; kt < 4; kt++) {
#pragma unroll
                for (int dg = 0; dg < 4; dg++) {
                    uint32_t vh[4], vl[4];
                    uint32_t va = st + 2 * ATT_TILE + (kt * 16 + vr) * ATT_PITCH + (dg * 16 + vc) * 2;
                    ldsm_x4_t(va, vh);
                    ldsm_x4_t(va + ATT_TILE, vl);
#pragma unroll
                    for (int hf = 0; hf < 2; hf++) {
                        float* d = o[dg * 2 + hf];
                        mma16816(d, phi[kt], &vh[hf * 2]);
                        mma16816(d, phi[kt], &vl[hf * 2]);
                        mma16816(d, plo[kt], &vh[hf * 2]);
                    }
                }
            }
        }
        __syncthreads();
        if (t + 2 < ntb) { issueTile(t + 2); CP_COMMIT(); }
    }

    // ---- normalize + store bf16 hi/lo --------------------------------------
    float inv0 = 1.f / l0, inv1 = 1.f / l1;
    int ro0 = wRow + (lane >> 2);
    size_t ob0 = ((size_t)(b * SEQ) + ro0) * D_MODEL + h * HDIM;
    size_t ob1 = ob0 + 8 * (size_t)D_MODEL;
#pragma unroll
    for (int nt = 0; nt < 8; nt++) {
        int c = nt * 8 + (lane & 3) * 2;
        uint32_t lo;
        uint32_t hi = packsplit(o[nt][0] * inv0, o[nt][1] * inv0, lo);
        *(uint32_t*)(OH + ob0 + c) = hi;
        *(uint32_t*)(OL + ob0 + c) = lo;
        hi = packsplit(o[nt][2] * inv1, o[nt][3] * inv1, lo);
        *(uint32_t*)(OH + ob1 + c) = hi;
        *(uint32_t*)(OL + ob1 + c) = lo;
    }
}

// ---------------------------------------------------------------------------
// Launch
// ---------------------------------------------------------------------------
extern "C" void kernel_launch(void* const* d_in, const int* in_sizes, int n_in,
                              void* d_out, int out_size)
{
    (void)in_sizes; (void)n_in; (void)out_size;
    const float* x     = (const float*)d_in[0];
    const float* wq    = (const float*)d_in[1];
    const float* bq    = (const float*)d_in[2];
    const float* wk    = (const float*)d_in[3];
    const float* bk    = (const float*)d_in[4];
    const float* wv    = (const float*)d_in[5];
    const float* bv    = (const float*)d_in[6];
    const float* wo    = (const float*)d_in[7];
    const float* bo    = (const float*)d_in[8];
    const float* w1    = (const float*)d_in[9];
    const float* b1    = (const float*)d_in[10];
    const float* w2    = (const float*)d_in[11];
    const float* b2    = (const float*)d_in[12];
    const float* ln1_g = (const float*)d_in[13];
    const float* ln1_b = (const float*)d_in[14];
    const float* ln2_g = (const float*)d_in[15];
    const float* ln2_b = (const float*)d_in[16];
    float* out = (float*)d_out;

    float *x1, *bqkv;
    __nv_bfloat16 *ln1h, *ln1l, *qkvh, *qkvl, *attnh, *attnl, *ln2h, *ln2l, *ff1h, *ff1l;
    __nv_bfloat16 *wqkvth, *wqkvtl, *woth, *wotl, *w1th, *w1tl, *w2th, *w2tl;
    cudaGetSymbolAddress((void**)&x1,   g_x1);
    cudaGetSymbolAddress((void**)&bqkv, g_bqkv);
    cudaGetSymbolAddress((void**)&ln1h, g_ln1h);  cudaGetSymbolAddress((void**)&ln1l, g_ln1l);
    cudaGetSymbolAddress((void**)&qkvh, g_qkvh);  cudaGetSymbolAddress((void**)&qkvl, g_qkvl);
    cudaGetSymbolAddress((void**)&attnh,g_attnh); cudaGetSymbolAddress((void**)&attnl,g_attnl);
    cudaGetSymbolAddress((void**)&ln2h, g_ln2h);  cudaGetSymbolAddress((void**)&ln2l, g_ln2l);
    cudaGetSymbolAddress((void**)&ff1h, g_ff1h);  cudaGetSymbolAddress((void**)&ff1l, g_ff1l);
    cudaGetSymbolAddress((void**)&wqkvth, g_wqkvth); cudaGetSymbolAddress((void**)&wqkvtl, g_wqkvtl);
    cudaGetSymbolAddress((void**)&woth, g_woth);  cudaGetSymbolAddress((void**)&wotl, g_wotl);
    cudaGetSymbolAddress((void**)&w1th, g_w1th);  cudaGetSymbolAddress((void**)&w1tl, g_w1tl);
    cudaGetSymbolAddress((void**)&w2th, g_w2th);  cudaGetSymbolAddress((void**)&w2tl, g_w2tl);

    cudaFuncSetAttribute(gemm_tc<false,false,false,true>,
                         cudaFuncAttributeMaxDynamicSharedMemorySize, GEMM_SMEM);
    cudaFuncSetAttribute(gemm_tc<false,true,true,false>,
                         cudaFuncAttributeMaxDynamicSharedMemorySize, GEMM_SMEM);
    cudaFuncSetAttribute(gemm_tc<true,false,false,true>,
                         cudaFuncAttributeMaxDynamicSharedMemorySize, GEMM_SMEM);
    cudaFuncSetAttribute(attn_tc,
                         cudaFuncAttributeMaxDynamicSharedMemorySize, ATT_SMEM);

    // fused QKV bias
    cudaMemcpyAsync(bqkv,             bq, D_MODEL * sizeof(float), cudaMemcpyDeviceToDevice);
    cudaMemcpyAsync(bqkv + D_MODEL,   bk, D_MODEL * sizeof(float), cudaMemcpyDeviceToDevice);
    cudaMemcpyAsync(bqkv + 2*D_MODEL, bv, D_MODEL * sizeof(float), cudaMemcpyDeviceToDevice);

    // all weight transposes + hi/lo splits in one launch
    wconv_all<<<6912, dim3(32, 8)>>>(wq, wk, wv, wo, w1, w2,
                                     wqkvth, wqkvtl, woth, wotl,
                                     w1th, w1tl, w2th, w2tl);

    // 1) LN1 -> bf16 hi/lo
    ln_kernel<<<MROWS, 256>>>(x, ln1_g, ln1_b, ln1h, ln1l);
    // 2) fused QKV projection -> bf16 hi/lo [4096, 2304]
    gemm_tc<false,false,false,true><<<dim3(LDQKV/64, MROWS/128), 256, GEMM_SMEM>>>(
        ln1h, ln1l, wqkvth, wqkvtl, bqkv, nullptr, nullptr, qkvh, qkvl, MROWS, LDQKV, D_MODEL);
    // 3) HMMA causal flash attention -> bf16 hi/lo
    attn_tc<<<dim3(SEQ/QROWS, NHEAD, BATCH), 256, ATT_SMEM>>>(qkvh, qkvl, attnh, attnl);
    // 4) O projection + residual (fp32 x1)
    gemm_tc<false,true,true,false><<<dim3(D_MODEL/64, MROWS/128), 256, GEMM_SMEM>>>(
        attnh, attnl, woth, wotl, bo, x, x1, nullptr, nullptr, MROWS, D_MODEL, D_MODEL);
    // 5) LN2 -> bf16 hi/lo
    ln_kernel<<<MROWS, 256>>>(x1, ln2_g, ln2_b, ln2h, ln2l);
    // 6) FFN up + ReLU -> bf16 hi/lo
    gemm_tc<true,false,false,true><<<dim3(D_FF/64, MROWS/128), 256, GEMM_SMEM>>>(
        ln2h, ln2l, w1th, w1tl, b1, nullptr, nullptr, ff1h, ff1l, MROWS, D_FF, D_MODEL);
    // 7) FFN down + residual -> output (fp32)
    gemm_tc<false,true,true,false><<<dim3(D_MODEL/64, MROWS/128), 256, GEMM_SMEM>>>(
        ff1h, ff1l, w2th, w2tl, b2, x1, out, nullptr, nullptr, MROWS, D_MODEL, D_FF);
}